// round 5
// baseline (speedup 1.0000x reference)
#include <cuda_runtime.h>
#include <math.h>

#define NUM_NODES 17185
#define D 6
#define FEATS (NUM_NODES * D)   // 103110
#define BATCH 256
#define NPB 64                  // nodes per block
#define GROUPS 8                // batch groups per block (512 threads)
#define ITERS (BATCH / GROUPS)  // 32 per-thread batch rows
#define NBLK ((NUM_NODES + NPB - 1) / NPB)  // 269
#define NBLK_PAD 272
#define EPS 1e-5f

// Transposed partials: g_partial[b * NBLK_PAD + blk] -> coalesced finalize reads.
// Written unconditionally every launch; __device__ global => no allocation.
__device__ float g_partial[BATCH * NBLK_PAD];

__global__ __launch_bounds__(512, 1)
void node_block_kernel(const float* __restrict__ data,
                       const float* __restrict__ w_blocks,
                       const float* __restrict__ b_blocks,
                       const float* __restrict__ bn_gamma,
                       const float* __restrict__ bn_beta,
                       const float* __restrict__ bn_mean,
                       const float* __restrict__ bn_var,
                       const float* __restrict__ fc_w)
{
    // Half the bi-range per round: 8 groups x 16 bi x 64 lanes = 32 KB
    __shared__ float sh[GROUPS][16][64];

    const int tid   = threadIdx.x;
    const int ln    = tid & 63;        // node lane
    const int group = tid >> 6;        // 0..7 batch sub-row
    const int node  = blockIdx.x * NPB + ln;
    const bool valid = (node < NUM_NODES);

    // Per-thread node state, loaded ONCE, reused for 32 batch rows.
    float W[36];
    float bias[D], A[D];
    float CN = 0.0f;

    if (valid) {
        const float4* wp = reinterpret_cast<const float4*>(w_blocks + (size_t)node * 36);
        #pragma unroll
        for (int i = 0; i < 9; ++i) {
            float4 v = __ldg(&wp[i]);
            W[i*4+0] = v.x; W[i*4+1] = v.y; W[i*4+2] = v.z; W[i*4+3] = v.w;
        }
        const int f0 = node * D;
        #pragma unroll
        for (int o = 0; o < D; ++o) {
            const int f = f0 + o;
            bias[o] = b_blocks[f];
            const float rs = rsqrtf(bn_var[f] + EPS);
            const float g  = bn_gamma[f] * rs;
            const float fw = fc_w[f];
            A[o]  = g * fw;
            CN   += (bn_beta[f] - bn_mean[f] * g) * fw;
        }
    }

    // Hot loop: pure loads + FMA. No shuffles, no syncs, no atomics.
    float vacc[ITERS];
    const float* p = data + (size_t)node * D + (size_t)group * FEATS;  // b = group

    #pragma unroll 2
    for (int bi = 0; bi < ITERS; ++bi) {
        float acc = 0.0f;
        if (valid) {
            const float2* xp = reinterpret_cast<const float2*>(p);
            const float2 x01 = __ldcs(&xp[0]);   // streaming: read-once data
            const float2 x23 = __ldcs(&xp[1]);
            const float2 x45 = __ldcs(&xp[2]);
            const float x[D] = {x01.x, x01.y, x23.x, x23.y, x45.x, x45.y};
            acc = CN;
            #pragma unroll
            for (int o = 0; o < D; ++o) {
                float s = bias[o];
                #pragma unroll
                for (int i = 0; i < D; ++i)
                    s = fmaf(x[i], W[o * D + i], s);
                s = fmaxf(s, 0.0f);        // ReLU
                acc = fmaf(s, A[o], acc);  // folded BN * fc_w
            }
        }
        vacc[bi] = acc;
        p += (size_t)GROUPS * FEATS;       // b += 8
    }

    // Epilogue: transpose-reduce over the 64 node lanes, 2 rounds x 16 bi.
    #pragma unroll
    for (int rd = 0; rd < 2; ++rd) {
        __syncthreads();   // protects smem reuse across rounds
        #pragma unroll
        for (int r = 0; r < 16; ++r)
            sh[group][r][ln] = vacc[rd * 16 + r];
        __syncthreads();

        if (tid < 128) {
            const int g  = tid & 7;
            const int bi = tid >> 3;                 // 0..15
            const int b  = (rd * 16 + bi) * GROUPS + g;
            const float* row = &sh[g][bi][0];
            float s = 0.0f;
            #pragma unroll
            for (int j = 0; j < 64; ++j)             // rotated -> conflict-free,
                s += row[(j + tid) & 63];            // fixed order -> deterministic
            g_partial[b * NBLK_PAD + blockIdx.x] = s;
        }
    }
}

__global__ void finalize_kernel(const float* __restrict__ fc_b,
                                const float* __restrict__ bnf_gamma,
                                const float* __restrict__ bnf_beta,
                                const float* __restrict__ bnf_mean,
                                const float* __restrict__ bnf_var,
                                float* __restrict__ out)
{
    const int b    = blockIdx.x;     // one block per batch row
    const int tid  = threadIdx.x;    // 64 threads
    const int lane = tid & 31;
    const int warp = tid >> 5;
    __shared__ float sh[2];

    float s = 0.0f;
    #pragma unroll 5
    for (int k = tid; k < NBLK; k += 64)          // coalesced, fixed order
        s += g_partial[b * NBLK_PAD + k];

    #pragma unroll
    for (int off = 16; off > 0; off >>= 1)
        s += __shfl_xor_sync(0xffffffffu, s, off);
    if (lane == 0) sh[warp] = s;
    __syncthreads();

    if (tid == 0) {
        float t = sh[0] + sh[1] + fc_b[0];
        const float rs = rsqrtf(bnf_var[0] + EPS);
        const float y  = (t - bnf_mean[0]) * rs * bnf_gamma[0] + bnf_beta[0];
        out[b] = 1.0f / (1.0f + expf(-y));
    }
}

extern "C" void kernel_launch(void* const* d_in, const int* in_sizes, int n_in,
                              void* d_out, int out_size) {
    const float* data      = (const float*)d_in[0];
    const float* w_blocks  = (const float*)d_in[1];
    const float* b_blocks  = (const float*)d_in[2];
    const float* bn_gamma  = (const float*)d_in[3];
    const float* bn_beta   = (const float*)d_in[4];
    const float* bn_mean   = (const float*)d_in[5];
    const float* bn_var    = (const float*)d_in[6];
    const float* fc_w      = (const float*)d_in[7];
    const float* fc_b      = (const float*)d_in[8];
    const float* bnf_gamma = (const float*)d_in[9];
    const float* bnf_beta  = (const float*)d_in[10];
    const float* bnf_mean  = (const float*)d_in[11];
    const float* bnf_var   = (const float*)d_in[12];
    float* out = (float*)d_out;

    node_block_kernel<<<NBLK, 512>>>(data, w_blocks, b_blocks, bn_gamma,
                                     bn_beta, bn_mean, bn_var, fc_w);
    finalize_kernel<<<BATCH, 64>>>(fc_b, bnf_gamma, bnf_beta, bnf_mean, bnf_var, out);
}